// round 1
// baseline (speedup 1.0000x reference)
#include <cuda_runtime.h>
#include <math.h>

#define Bn 4
#define Mn 1024
#define Nn 70
#define Dn 256
#define Hn 8
#define Ln 4
#define DFFn 1024
#define DKn 32

// ---------------- scratch (no cudaMalloc allowed) ----------------
__device__ float g_x[Bn * Mn * Dn];
__device__ float g_xn[Bn * Mn * Dn];
__device__ float g_q[Bn * Mn * Dn];
__device__ float g_k[Bn * Mn * Dn];
__device__ float g_v[Bn * Mn * Dn];
__device__ float g_att[Bn * Mn * Dn];
__device__ float g_hid[Bn * Mn * DFFn];
__device__ float g_scores[(size_t)Bn * Hn * Mn * Mn];
__device__ float g_attw[(size_t)Bn * Hn * Mn * Mn];
__device__ float g_stmp[(size_t)Bn * Mn * Mn];

// ---------------- embedding: fourier PE + char projection ----------------
__global__ void embed_kernel(const float* __restrict__ X,
                             const float* __restrict__ fW,
                             const float* __restrict__ fb,
                             const float* __restrict__ cW,
                             const float* __restrict__ cb) {
    int row = blockIdx.x;          // b*M + m
    int d = threadIdx.x;           // 0..255
    __shared__ float xr[Nn];
    if (d < Nn) xr[d] = X[(size_t)row * Nn + d];
    __syncthreads();

    int j = d & 127;
    float p = xr[0] * fW[j * 3 + 0] + xr[1] * fW[j * 3 + 1] + xr[2] * fW[j * 3 + 2] + fb[j];
    float pe = (d < 128 ? cosf(p) : sinf(p)) * 0.17677669529663687f;  // sqrt(2/64)

    float acc = cb[d] + pe;
#pragma unroll
    for (int c = 0; c < 64; c++) acc += xr[6 + c] * cW[c * Dn + d];
    g_x[(size_t)row * Dn + d] = acc;
}

// ---------------- layernorm over D=256, one block per row ----------------
__global__ void ln_kernel(const float* __restrict__ x,
                          const float* __restrict__ w,
                          const float* __restrict__ b,
                          float* __restrict__ out) {
    int row = blockIdx.x;
    int t = threadIdx.x;
    float v = x[(size_t)row * Dn + t];
    __shared__ float red[256];
    red[t] = v;
    __syncthreads();
    for (int s = 128; s > 0; s >>= 1) {
        if (t < s) red[t] += red[t + s];
        __syncthreads();
    }
    float mu = red[0] * (1.0f / Dn);
    __syncthreads();
    float dv = v - mu;
    red[t] = dv * dv;
    __syncthreads();
    for (int s = 128; s > 0; s >>= 1) {
        if (t < s) red[t] += red[t + s];
        __syncthreads();
    }
    float var = red[0] * (1.0f / Dn);
    float r = rsqrtf(var + 1e-5f);
    out[(size_t)row * Dn + t] = dv * r * w[t] + b[t];
}

// ---------------- generic tiled GEMM: C = A[MxK] @ B[KxN] + bias (+gelu) (+res) ----------------
// M,N multiples of 64; K multiple of 16 (true for all calls here).
template <bool GELU, bool RES>
__global__ void gemm_kernel(const float* __restrict__ A, const float* __restrict__ B,
                            const float* __restrict__ bias, const float* __restrict__ res,
                            float* __restrict__ C, int M, int N, int K) {
    const int BM = 64, BN = 64, BK = 16;
    __shared__ float As[BM][BK + 1];
    __shared__ float Bs[BK][BN];
    int bm = blockIdx.y * BM, bn = blockIdx.x * BN;
    int tid = threadIdx.x;
    int ty = tid / 16, tx = tid % 16;
    float acc[4][4] = {};

    for (int k0 = 0; k0 < K; k0 += BK) {
#pragma unroll
        for (int i = 0; i < 4; i++) {
            int idx = tid + i * 256;
            int r = idx / BK, c = idx % BK;
            As[r][c] = A[(size_t)(bm + r) * K + k0 + c];
        }
#pragma unroll
        for (int i = 0; i < 4; i++) {
            int idx = tid + i * 256;
            int r = idx / BN, c = idx % BN;
            Bs[r][c] = B[(size_t)(k0 + r) * N + bn + c];
        }
        __syncthreads();
#pragma unroll
        for (int kk = 0; kk < BK; kk++) {
            float a[4], bb[4];
#pragma unroll
            for (int i = 0; i < 4; i++) a[i] = As[ty * 4 + i][kk];
#pragma unroll
            for (int j = 0; j < 4; j++) bb[j] = Bs[kk][tx * 4 + j];
#pragma unroll
            for (int i = 0; i < 4; i++)
#pragma unroll
                for (int j = 0; j < 4; j++) acc[i][j] += a[i] * bb[j];
        }
        __syncthreads();
    }
#pragma unroll
    for (int i = 0; i < 4; i++) {
        int r = bm + ty * 4 + i;
#pragma unroll
        for (int j = 0; j < 4; j++) {
            int cn = bn + tx * 4 + j;
            float v = acc[i][j] + bias[cn];
            if (GELU) v = 0.5f * v * (1.0f + erff(v * 0.70710678118654752f));
            if (RES) v += res[(size_t)r * N + cn];
            C[(size_t)r * N + cn] = v;
        }
    }
}

// ---------------- scores[b,h,q,k] = (Q . K) / sqrt(32) ----------------
__global__ void scores_kernel(const float* __restrict__ q, const float* __restrict__ k,
                              float* __restrict__ scores) {
    int bh = blockIdx.z;
    int b = bh / Hn, h = bh % Hn;
    int q0 = blockIdx.y * 64, k0 = blockIdx.x * 64;
    __shared__ float Qs[64][33], Ks[64][33];
    int tid = threadIdx.x;
#pragma unroll
    for (int i = 0; i < 8; i++) {
        int idx = tid + i * 256;
        int r = idx / 32, c = idx % 32;
        Qs[r][c] = q[(size_t)(b * Mn + q0 + r) * Dn + h * DKn + c];
        Ks[r][c] = k[(size_t)(b * Mn + k0 + r) * Dn + h * DKn + c];
    }
    __syncthreads();
    int ty = tid / 16, tx = tid % 16;
    float acc[4][4] = {};
#pragma unroll
    for (int c = 0; c < 32; c++) {
        float a[4], bb[4];
#pragma unroll
        for (int i = 0; i < 4; i++) a[i] = Qs[ty * 4 + i][c];
#pragma unroll
        for (int j = 0; j < 4; j++) bb[j] = Ks[tx * 4 + j][c];
#pragma unroll
        for (int i = 0; i < 4; i++)
#pragma unroll
            for (int j = 0; j < 4; j++) acc[i][j] += a[i] * bb[j];
    }
    const float sc = 0.17677669529663687f;  // 1/sqrt(32)
    size_t base = ((size_t)(b * Hn + h) * Mn + q0) * Mn + k0;
#pragma unroll
    for (int i = 0; i < 4; i++)
#pragma unroll
        for (int j = 0; j < 4; j++)
            scores[base + (size_t)(ty * 4 + i) * Mn + tx * 4 + j] = acc[i][j] * sc;
}

// ---------------- masked softmax over k (row = (b*H+h)*M + q) ----------------
__global__ void softmax_kernel(const float* __restrict__ scores, const int* __restrict__ mask,
                               float* __restrict__ attw) {
    int row = blockIdx.x;
    int qq = row % Mn;
    int b = row / (Hn * Mn);
    const float* s = scores + (size_t)row * Mn;
    const int* mrow = mask + ((size_t)b * Mn + qq) * Mn;
    int t = threadIdx.x;
    float v[4];
    float mx = -1e30f;
#pragma unroll
    for (int i = 0; i < 4; i++) {
        int kk = t + i * 256;
        float val = (mrow[kk] == 0) ? -1e30f : s[kk];
        v[i] = val;
        mx = fmaxf(mx, val);
    }
    __shared__ float red[256];
    red[t] = mx;
    __syncthreads();
    for (int st = 128; st > 0; st >>= 1) {
        if (t < st) red[t] = fmaxf(red[t], red[t + st]);
        __syncthreads();
    }
    mx = red[0];
    __syncthreads();
    float sum = 0.f;
#pragma unroll
    for (int i = 0; i < 4; i++) {
        v[i] = expf(v[i] - mx);
        sum += v[i];
    }
    red[t] = sum;
    __syncthreads();
    for (int st = 128; st > 0; st >>= 1) {
        if (t < st) red[t] += red[t + st];
        __syncthreads();
    }
    float inv = 1.0f / red[0];
    float* o = attw + (size_t)row * Mn;
#pragma unroll
    for (int i = 0; i < 4; i++) o[t + i * 256] = v[i] * inv;
}

// ---------------- att[b,m,h*32+d] = sum_k attw[b,h,m,k] * v[b,k,h*32+d] ----------------
__global__ void attv_kernel(const float* __restrict__ w, const float* __restrict__ v,
                            float* __restrict__ att) {
    int bh = blockIdx.y;
    int b = bh / Hn, h = bh % Hn;
    int m0 = blockIdx.x * 64;
    __shared__ float Ws[64][65];
    __shared__ float Vs[64][33];
    int tid = threadIdx.x;
    int d = tid % 32, rg = tid / 32;
    float acc[8] = {};
    const float* wbase = w + ((size_t)(b * Hn + h) * Mn + m0) * Mn;
    for (int kt = 0; kt < Mn; kt += 64) {
#pragma unroll
        for (int i = 0; i < 16; i++) {
            int idx = tid + i * 256;
            int r = idx / 64, c = idx % 64;
            Ws[r][c] = wbase[(size_t)r * Mn + kt + c];
        }
#pragma unroll
        for (int i = 0; i < 8; i++) {
            int idx = tid + i * 256;
            int r = idx / 32, c = idx % 32;
            Vs[r][c] = v[(size_t)(b * Mn + kt + r) * Dn + h * DKn + c];
        }
        __syncthreads();
#pragma unroll
        for (int kk = 0; kk < 64; kk++) {
            float vv = Vs[kk][d];
#pragma unroll
            for (int j = 0; j < 8; j++) acc[j] += Ws[rg * 8 + j][kk] * vv;
        }
        __syncthreads();
    }
#pragma unroll
    for (int j = 0; j < 8; j++)
        att[(size_t)(b * Mn + m0 + rg * 8 + j) * Dn + h * DKn + d] = acc[j];
}

// ---------------- s head part 1: per (b,q,k) LN over H + projection ----------------
__global__ void spool_kernel(const float* __restrict__ scores, const float* __restrict__ snw,
                             const float* __restrict__ snb, const float* __restrict__ sfpw,
                             const float* __restrict__ sfpb, float* __restrict__ tmp) {
    size_t idx = (size_t)blockIdx.x * blockDim.x + threadIdx.x;
    if (idx >= (size_t)Bn * Mn * Mn) return;
    int k = idx % Mn;
    size_t r = idx / Mn;
    int qq = (int)(r % Mn);
    int b = (int)(r / Mn);
    float vals[8];
    float mu = 0.f;
#pragma unroll
    for (int h = 0; h < 8; h++) {
        vals[h] = scores[((size_t)(b * Hn + h) * Mn + qq) * Mn + k];
        mu += vals[h];
    }
    mu *= 0.125f;
    float var = 0.f;
#pragma unroll
    for (int h = 0; h < 8; h++) {
        float dd = vals[h] - mu;
        var += dd * dd;
    }
    var *= 0.125f;
    float rs = rsqrtf(var + 1e-5f);
    float o = sfpb[0];
#pragma unroll
    for (int h = 0; h < 8; h++) o += ((vals[h] - mu) * rs * snw[h] + snb[h]) * sfpw[h];
    tmp[idx] = o;
}

// ---------------- s head part 2: symmetrize ----------------
__global__ void ssym_kernel(const float* __restrict__ tmp, float* __restrict__ out) {
    size_t idx = (size_t)blockIdx.x * blockDim.x + threadIdx.x;
    if (idx >= (size_t)Bn * Mn * Mn) return;
    int k = idx % Mn;
    size_t r = idx / Mn;
    int qq = (int)(r % Mn);
    int b = (int)(r / Mn);
    out[idx] = 0.5f * (tmp[idx] + tmp[((size_t)b * Mn + k) * Mn + qq]);
}

// =====================================================================
extern "C" void kernel_launch(void* const* d_in, const int* in_sizes, int n_in,
                              void* d_out, int out_size) {
    const float* X   = (const float*)d_in[0];
    const int*   mask= (const int*)d_in[1];
    const float* fW  = (const float*)d_in[2];
    const float* fb  = (const float*)d_in[3];
    const float* cW  = (const float*)d_in[4];
    const float* cb  = (const float*)d_in[5];
    const float* Wq  = (const float*)d_in[6];
    const float* bq  = (const float*)d_in[7];
    const float* Wk  = (const float*)d_in[8];
    const float* bk  = (const float*)d_in[9];
    const float* Wv  = (const float*)d_in[10];
    const float* bv  = (const float*)d_in[11];
    const float* Wo  = (const float*)d_in[12];
    const float* bo  = (const float*)d_in[13];
    const float* ln1w= (const float*)d_in[14];
    const float* ln1b= (const float*)d_in[15];
    const float* ln2w= (const float*)d_in[16];
    const float* ln2b= (const float*)d_in[17];
    const float* lnfw= (const float*)d_in[18];
    const float* lnfb= (const float*)d_in[19];
    const float* uw  = (const float*)d_in[20];
    const float* ub  = (const float*)d_in[21];
    const float* dw  = (const float*)d_in[22];
    const float* db  = (const float*)d_in[23];
    const float* finw= (const float*)d_in[24];
    const float* finb= (const float*)d_in[25];
    const float* snw = (const float*)d_in[26];
    const float* snb = (const float*)d_in[27];
    const float* sfpw= (const float*)d_in[28];
    const float* sfpb= (const float*)d_in[29];

    float *x, *xn, *q, *k, *v, *att, *hid, *scores, *attw, *stmp;
    cudaGetSymbolAddress((void**)&x, g_x);
    cudaGetSymbolAddress((void**)&xn, g_xn);
    cudaGetSymbolAddress((void**)&q, g_q);
    cudaGetSymbolAddress((void**)&k, g_k);
    cudaGetSymbolAddress((void**)&v, g_v);
    cudaGetSymbolAddress((void**)&att, g_att);
    cudaGetSymbolAddress((void**)&hid, g_hid);
    cudaGetSymbolAddress((void**)&scores, g_scores);
    cudaGetSymbolAddress((void**)&attw, g_attw);
    cudaGetSymbolAddress((void**)&stmp, g_stmp);

    const int BM = Bn * Mn;  // 4096 rows

    embed_kernel<<<BM, 256>>>(X, fW, fb, cW, cb);

    for (int i = 0; i < Ln; i++) {
        const float* Wqi = Wq + (size_t)i * Dn * Dn;
        const float* Wki = Wk + (size_t)i * Dn * Dn;
        const float* Wvi = Wv + (size_t)i * Dn * Dn;
        const float* Woi = Wo + (size_t)i * Dn * Dn;
        const float* uwi = uw + (size_t)i * Dn * DFFn;
        const float* dwi = dw + (size_t)i * DFFn * Dn;

        ln_kernel<<<BM, 256>>>(x, ln1w + i * Dn, ln1b + i * Dn, xn);

        dim3 gq(Dn / 64, BM / 64);
        gemm_kernel<false, false><<<gq, 256>>>(xn, Wqi, bq + i * Dn, nullptr, q, BM, Dn, Dn);
        gemm_kernel<false, false><<<gq, 256>>>(xn, Wki, bk + i * Dn, nullptr, k, BM, Dn, Dn);
        gemm_kernel<false, false><<<gq, 256>>>(xn, Wvi, bv + i * Dn, nullptr, v, BM, Dn, Dn);

        dim3 gs(Mn / 64, Mn / 64, Bn * Hn);
        scores_kernel<<<gs, 256>>>(q, k, scores);

        softmax_kernel<<<Bn * Hn * Mn, 256>>>(scores, mask, attw);

        dim3 ga(Mn / 64, Bn * Hn);
        attv_kernel<<<ga, 256>>>(attw, v, att);

        gemm_kernel<false, true><<<gq, 256>>>(att, Woi, bo + i * Dn, x, x, BM, Dn, Dn);

        ln_kernel<<<BM, 256>>>(x, ln2w + i * Dn, ln2b + i * Dn, xn);

        dim3 gu(DFFn / 64, BM / 64);
        gemm_kernel<true, false><<<gu, 256>>>(xn, uwi, ub + i * DFFn, nullptr, hid, BM, DFFn, Dn);

        gemm_kernel<false, true><<<gq, 256>>>(hid, dwi, db + i * Dn, x, x, BM, Dn, DFFn);
    }

    float* out_x = (float*)d_out;                    // (B, M, 64)
    float* out_s = out_x + (size_t)BM * 64;          // (B, M, M)

    ln_kernel<<<BM, 256>>>(x, lnfw, lnfb, xn);
    dim3 gf(64 / 64, BM / 64);
    gemm_kernel<false, false><<<gf, 256>>>(xn, finw, finb, nullptr, out_x, BM, 64, Dn);

    size_t npair = (size_t)Bn * Mn * Mn;
    int nb = (int)((npair + 255) / 256);
    spool_kernel<<<nb, 256>>>(scores, snw, snb, sfpw, sfpb, stmp);
    ssym_kernel<<<nb, 256>>>(stmp, out_s);
}